// round 6
// baseline (speedup 1.0000x reference)
#include <cuda_runtime.h>

#define SCALING 2.0f     // alpha / r = 32 / 16
#define TOK     16384

// scratch (allocation-free rule: __device__ globals)
__device__ float g_v[TOK * 32];   // per token: [ s*g1*ce[0:16] | s*g2*ce[0:16] ]
__device__ int   g_eidx[TOK];     // e1 | (e2 << 8)

static __device__ __forceinline__ unsigned long long ffma2(unsigned long long a,
                                                           unsigned long long b,
                                                           unsigned long long c) {
    unsigned long long d;
    asm("fma.rn.f32x2 %0, %1, %2, %3;" : "=l"(d) : "l"(a), "l"(b), "l"(c));
    return d;
}

union F4  { float4 f; unsigned long long u[2]; };
union U2F { unsigned long long u; float2 f; };

// ---------------------------------------------------------------------------
// Kernel 1: logits(8) + ce(16) + routing.
// CTA = 256 thr = 8 warps; warp = k-slice (128 k), lane = 2 tokens (lane,
// lane+32) of a 64-token group. Weights broadcast from smem (each weight LDS
// feeds 2 tokens); x double-buffered + swizzled; sred overlaid on x tile.
// ---------------------------------------------------------------------------
#define K1_SW_F4   6144                      // 24 rows * 256 f4
#define K1_XB_F4   2048                      // one buffer: 64 tok * 32 f4
#define K1_SMEM    ((K1_SW_F4 + 2 * K1_XB_F4) * 16)   // 163840 B

__global__ void __launch_bounds__(256, 1)
k_route(const float4* __restrict__ X4,   // x: row = 256 f4
        const float4* __restrict__ WR4,  // w_route: 2048 f4
        const float4* __restrict__ CP4,  // compress: 4096 f4
        int ngroups)                     // 64-token groups
{
    extern __shared__ float4 sm4[];
    float4* sW   = sm4;                       // [24][256]
    float4* sX   = sm4 + K1_SW_F4;            // 2 x [64][32] (swizzled)
    float*  sred = (float*)sX;                // overlay: [24][8][64] = 48KB

    const int tid   = threadIdx.x;
    const int lane  = tid & 31;
    const int ks    = tid >> 5;               // k-slice warp
    const int stok0 = tid >> 5;               // staging token = stok0 + 8j
    const int scol  = tid & 31;               // staging f4 col

    for (int i = tid; i < 2048; i += 256) sW[i]        = WR4[i];
    for (int i = tid; i < 4096; i += 256) sW[2048 + i] = CP4[i];

    for (int g = blockIdx.x; g < ngroups; g += gridDim.x) {
        const int tb = g * 64;
        float4 st[8];

        // prologue: chunk 0 -> buf 0  (sX safe: Sr3 of prev group passed)
        {
            const float4* xb = X4 + (size_t)tb * 256;
#pragma unroll
            for (int j = 0; j < 8; j++)
                st[j] = xb[(size_t)(stok0 + 8 * j) * 256 + scol];
#pragma unroll
            for (int j = 0; j < 8; j++) {
                int tok = stok0 + 8 * j;
                sX[tok * 32 + (scol ^ (tok & 31))] = st[j];
            }
        }
        __syncthreads();   // S1 (also covers sW on first group)

        unsigned long long acc[48];
#pragma unroll
        for (int o = 0; o < 48; o++) acc[o] = 0ull;

        for (int c = 0; c < 8; c++) {
            if (c < 7) {
                const float4* xb = X4 + (size_t)tb * 256 + (c + 1) * 32;
#pragma unroll
                for (int j = 0; j < 8; j++)
                    st[j] = xb[(size_t)(stok0 + 8 * j) * 256 + scol];
            }
            const float4* xbuf = sX + (c & 1) * K1_XB_F4;
            const float4* wb   = sW + c * 32 + ks * 4;
#pragma unroll
            for (int b = 0; b < 4; b++) {
                const int f4i = ks * 4 + b;
                F4 xa, xc;
                xa.f = xbuf[lane * 32 + (f4i ^ lane)];          // token lane
                xc.f = xbuf[(lane + 32) * 32 + (f4i ^ lane)];   // token lane+32
#pragma unroll
                for (int o = 0; o < 24; o++) {
                    F4 w; w.f = wb[o * 256 + b];                // broadcast
                    acc[o]      = ffma2(w.u[0], xa.u[0], acc[o]);
                    acc[o]      = ffma2(w.u[1], xa.u[1], acc[o]);
                    acc[24 + o] = ffma2(w.u[0], xc.u[0], acc[24 + o]);
                    acc[24 + o] = ffma2(w.u[1], xc.u[1], acc[24 + o]);
                }
            }
            if (c < 7) {
                // write buf (c+1)&1: last read at iter c-1, separated by the
                // sync below of that iteration -> single sync per chunk.
#pragma unroll
                for (int j = 0; j < 8; j++) {
                    int tok = stok0 + 8 * j;
                    sX[((c + 1) & 1) * K1_XB_F4 + tok * 32 + (scol ^ (tok & 31))] = st[j];
                }
                __syncthreads();
            }
        }
        __syncthreads();   // Sr1: all x reads done; sX reusable as sred

#pragma unroll
        for (int o = 0; o < 24; o++) {
            U2F ua, uc;
            ua.u = acc[o];      sred[o * 512 + ks * 64 + lane]      = ua.f.x + ua.f.y;
            uc.u = acc[24 + o]; sred[o * 512 + ks * 64 + lane + 32] = uc.f.x + uc.f.y;
        }
        __syncthreads();   // Sr2

        if (ks < 2) {      // warps 0,1: 64 tokens, finish reduce + route
            const int tok = ks * 32 + lane;
            float red[24];
#pragma unroll
            for (int o = 0; o < 24; o++) {
                float s = 0.f;
#pragma unroll
                for (int k8 = 0; k8 < 8; k8++) s += sred[o * 512 + k8 * 64 + tok];
                red[o] = s;
            }
            int e1 = 0; float v1 = red[0];
#pragma unroll
            for (int e = 1; e < 8; e++) if (red[e] > v1) { v1 = red[e]; e1 = e; }
            int e2 = 0; float v2 = -3.0e38f;
#pragma unroll
            for (int e = 0; e < 8; e++) if (e != e1 && red[e] > v2) { v2 = red[e]; e2 = e; }
            float ex  = __expf(v2 - v1);
            float inv = 1.0f / (1.0f + ex);
            float sg1 = SCALING * inv;
            float sg2 = SCALING * ex * inv;
            const int t = tb + tok;
            float4* vo = (float4*)(g_v + (size_t)t * 32);
#pragma unroll
            for (int j = 0; j < 4; j++)
                vo[j] = make_float4(sg1 * red[8 + j * 4], sg1 * red[9 + j * 4],
                                    sg1 * red[10 + j * 4], sg1 * red[11 + j * 4]);
#pragma unroll
            for (int j = 0; j < 4; j++)
                vo[4 + j] = make_float4(sg2 * red[8 + j * 4], sg2 * red[9 + j * 4],
                                        sg2 * red[10 + j * 4], sg2 * red[11 + j * 4]);
            g_eidx[t] = e1 | (e2 << 8);
        }
        __syncthreads();   // Sr3: sred reads done before next group's STS
    }
}

// ---------------------------------------------------------------------------
// Kernel 2: expert-major combine. CTA = 32 tokens x 256 cols, 128 threads,
// thread owns adjacent col pair (2*tid, 2*tid+1). Expert weights in regs,
// float2 smem RMW, 5-6 CTAs/SM.
// ---------------------------------------------------------------------------
#define K2T      32
#define K2_SMEM  (K2T*256*4 + K2T*32*4 + 8*K2T*4 + K2T*4 + 8*4)   // 38048 B

__global__ void __launch_bounds__(128)
k_combine(const float4* __restrict__ R4,   // routed: [8][1024][16] -> e*4096 + o*4
          float4* __restrict__ out4)       // out: row = 256 f4
{
    extern __shared__ float sm[];
    float* sacc  = sm;                      // [32][256]
    float* sv    = sm + K2T * 256;          // [32][32]
    int*   slist = (int*)(sv + K2T * 32);   // [8][32]
    int*   se    = slist + 8 * K2T;         // [32]
    int*   scnt  = se + K2T;                // [8]

    const int tid = threadIdx.x;
    const int cb  = blockIdx.x;             // 0..3
    const int t0  = blockIdx.y * K2T;

    if (tid < K2T) se[tid] = g_eidx[t0 + tid];
    {
        const float4* vg = (const float4*)(g_v + (size_t)t0 * 32);
        float4* sv4 = (float4*)sv;
#pragma unroll
        for (int i = tid; i < K2T * 8; i += 128) sv4[i] = vg[i];
    }
    __syncthreads();

    if (tid == 0) {                         // deterministic serial list build
        int c[8] = {0,0,0,0,0,0,0,0};
        for (int t = 0; t < K2T; t++) {
            int ee = se[t];
            int e1 = ee & 255, e2 = (ee >> 8) & 255;
            slist[e1 * K2T + c[e1]++] = t;
            slist[e2 * K2T + c[e2]++] = t | K2T;   // bit5 = second-expert half
        }
#pragma unroll
        for (int e = 0; e < 8; e++) scnt[e] = c[e];
    } else {
        float4 z = make_float4(0.f, 0.f, 0.f, 0.f);
        float4* sa4 = (float4*)sacc;
        for (int i = tid - 1; i < K2T * 64; i += 127) sa4[i] = z;
    }
    __syncthreads();

    const int o0 = cb * 256 + tid * 2;      // cols o0, o0+1 (adjacent)
    float2* sacc2 = (float2*)sacc;
    for (int e = 0; e < 8; e++) {
        const int n = scnt[e];
        if (!n) continue;
        F4 a0, a1, a2, a3, b0, b1, b2, b3;
        const float4* W = R4 + (size_t)e * 4096 + (size_t)o0 * 4;
        a0.f = W[0]; a1.f = W[1]; a2.f = W[2]; a3.f = W[3];   // col o0
        b0.f = W[4]; b1.f = W[5]; b2.f = W[6]; b3.f = W[7];   // col o0+1
        const int* lst = slist + e * K2T;
        int ent = lst[0];
#pragma unroll 2
        for (int k = 0; k < n; k++) {
            int entn = lst[(k + 1 < n) ? (k + 1) : k];        // prefetch
            int tl   = ent & 31;
            const F4* v = (const F4*)(sv + tl * 32 + ((ent & K2T) >> 1));
            F4 v0 = v[0], v1 = v[1], v2 = v[2], v3 = v[3];    // broadcast LDS128
            unsigned long long x = 0ull, y = 0ull;
            x = ffma2(a0.u[0], v0.u[0], x); x = ffma2(a0.u[1], v0.u[1], x);
            x = ffma2(a1.u[0], v1.u[0], x); x = ffma2(a1.u[1], v1.u[1], x);
            x = ffma2(a2.u[0], v2.u[0], x); x = ffma2(a2.u[1], v2.u[1], x);
            x = ffma2(a3.u[0], v3.u[0], x); x = ffma2(a3.u[1], v3.u[1], x);
            y = ffma2(b0.u[0], v0.u[0], y); y = ffma2(b0.u[1], v0.u[1], y);
            y = ffma2(b1.u[0], v1.u[0], y); y = ffma2(b1.u[1], v1.u[1], y);
            y = ffma2(b2.u[0], v2.u[0], y); y = ffma2(b2.u[1], v2.u[1], y);
            y = ffma2(b3.u[0], v3.u[0], y); y = ffma2(b3.u[1], v3.u[1], y);
            U2F ux, uy; ux.u = x; uy.u = y;
            float2* ac = sacc2 + tl * 128 + tid;              // exclusive slot
            float2 A = *ac;
            A.x += ux.f.x + ux.f.y;
            A.y += uy.f.x + uy.f.y;
            *ac = A;
            ent = entn;
        }
    }
    __syncthreads();

    const float4* sa4 = (const float4*)sacc;
#pragma unroll
    for (int i = tid; i < K2T * 64; i += 128) {
        int tl = i >> 6, c4 = i & 63;
        out4[(size_t)(t0 + tl) * 256 + cb * 64 + c4] = sa4[i];
    }
}

// ---------------------------------------------------------------------------
// Launch. Inputs identified by element count (all distinct):
//   x = 16777216, w_route = 8192, compress = 16384, routed = 131072
// ---------------------------------------------------------------------------
extern "C" void kernel_launch(void* const* d_in, const int* in_sizes, int n_in,
                              void* d_out, int out_size) {
    const float *x = nullptr, *wr = nullptr, *cp = nullptr, *rt = nullptr;
    long long n_x = 0;
    for (int i = 0; i < n_in; i++) {
        int s = in_sizes[i];
        if      (s == 8192)   wr = (const float*)d_in[i];
        else if (s == 16384)  cp = (const float*)d_in[i];
        else if (s == 131072) rt = (const float*)d_in[i];
        else { x = (const float*)d_in[i]; n_x = s; }
    }
    const int n_tok = (int)(n_x / 1024);   // 16384

    cudaFuncSetAttribute(k_route,   cudaFuncAttributeMaxDynamicSharedMemorySize, K1_SMEM);
    cudaFuncSetAttribute(k_combine, cudaFuncAttributeMaxDynamicSharedMemorySize, K2_SMEM);

    k_route<<<148, 256, K1_SMEM>>>((const float4*)x, (const float4*)wr,
                                   (const float4*)cp, n_tok / 64);

    dim3 g2(4, n_tok / K2T);
    k_combine<<<g2, 128, K2_SMEM>>>((const float4*)rt, (float4*)d_out);
}